// round 1
// baseline (speedup 1.0000x reference)
#include <cuda_runtime.h>
#include <math.h>

#define BB 4
#define EE 100000
#define TT 100000
#define RR 500
#define DD 64
#define NSTEPS 2
#define EPSV 1e-6f

// Scratch (zero at module load; every executed launch restores zeros it dirtied)
__device__ float g_ep0[BB * EE];                 // 1.6 MB
__device__ float g_ep1[BB * EE];                 // 1.6 MB
__device__ float g_hist[(size_t)BB * EE * DD];   // 102.4 MB, sparse-touched
__device__ float g_xproj[RR * 3 * DD];           // per-relation x_proj
__device__ float g_cqw[NSTEPS * BB * DD];        // tanh(q@W+b) * w_cls
__device__ int   g_cnt0, g_cnt1;
__device__ int   g_list0[BB * TT];               // active (b,t) step 0
__device__ int   g_list1[BB * TT];               // active (b,t) step 1

__device__ __forceinline__ float sigmoidf_(float x) { return 1.f / (1.f + expf(-x)); }

// ---- K1: per-relation x_proj, per-(step,batch) cqw, counter reset --------
__global__ void k_precompute(const float* __restrict__ rel_emb,
                             const float* __restrict__ W_step,
                             const float* __restrict__ b_step,
                             const float* __restrict__ w_ih,
                             const float* __restrict__ b_ih,
                             const float* __restrict__ w_cls,
                             const int*   __restrict__ query) {
    __shared__ float sm[BB * DD];
    int blk = blockIdx.x, tid = threadIdx.x;
    if (blk < RR) {
        if (tid < DD) sm[tid] = rel_emb[blk * DD + tid];
        __syncthreads();
        float acc = b_ih[tid];                       // tid in [0,192)
        const float* w = w_ih + tid * DD;
        #pragma unroll
        for (int k = 0; k < DD; k++) acc = fmaf(w[k], sm[k], acc);
        g_xproj[blk * 3 * DD + tid] = acc;
    } else {
        for (int i = tid; i < BB * DD; i += blockDim.x) {
            int b = i / DD, dd = i % DD;
            sm[i] = rel_emb[query[b] * DD + dd];
        }
        __syncthreads();
        for (int idx = tid; idx < NSTEPS * BB * DD; idx += blockDim.x) {
            int s = idx / (BB * DD);
            int rem = idx % (BB * DD);
            int b = rem / DD, dd = rem % DD;
            float acc = b_step[s * DD + dd];
            const float* W = W_step + s * DD * DD;
            #pragma unroll 8
            for (int k = 0; k < DD; k++) acc = fmaf(sm[b * DD + k], W[k * DD + dd], acc);
            g_cqw[idx] = tanhf(acc) * w_cls[dd];
        }
        if (tid == 0) { g_cnt0 = 0; g_cnt1 = 0; }
    }
}

// ---- K2/K4: frontier scan ------------------------------------------------
__global__ void k_scan(const int* __restrict__ kb, const float* __restrict__ start,
                       int step) {
    int t = blockIdx.x * blockDim.x + threadIdx.x;
    if (t >= TT) return;
    int s = kb[3 * t];
    #pragma unroll
    for (int b = 0; b < BB; b++) {
        float le;
        if (step == 0) {
            le = start[b * EE + s];
        } else {
            float x = g_ep0[b * EE + s];
            le = x > 1.f ? 1.f : x;
        }
        if (le != 0.f) {
            if (step == 0) { int i = atomicAdd(&g_cnt0, 1); g_list0[i] = (b << 20) | t; }
            else           { int i = atomicAdd(&g_cnt1, 1); g_list1[i] = (b << 20) | t; }
        }
    }
}

// ---- K3/K5: GRU transfer on active edges (64 threads = one edge) ---------
__global__ void k_gru(const int* __restrict__ kb, const float* __restrict__ start,
                      const float* __restrict__ w_hh, const float* __restrict__ b_hh,
                      const float* __restrict__ b_cls, int step) {
    __shared__ float sh[DD];
    __shared__ float red[2];
    int d = threadIdx.x;  // 0..63
    const int* list = step ? g_list1 : g_list0;
    int cnt = step ? g_cnt1 : g_cnt0;
    for (int i = blockIdx.x; i < cnt; i += gridDim.x) {
        __syncthreads();  // guard sh/red reuse across iterations
        int code = list[i];
        int b = code >> 20, t = code & 0xFFFFF;
        int s = kb[3 * t], o = kb[3 * t + 1], r = kb[3 * t + 2];
        float le, hd;
        if (step == 0) {
            hd = 0.f;
            le = start[b * EE + s];
        } else {
            float ep = g_ep0[b * EE + s];
            hd = g_hist[(size_t)(b * EE + s) * DD + d] / (ep + EPSV);
            le = ep > 1.f ? 1.f : ep;
        }
        sh[d] = hd;
        __syncthreads();
        float hr = b_hh[d], hz = b_hh[DD + d], hn = b_hh[2 * DD + d];
        if (step) {  // step 0: h == 0 exactly, h_proj == b_hh
            const float* w0 = w_hh + d * DD;
            const float* w1 = w_hh + (DD + d) * DD;
            const float* w2 = w_hh + (2 * DD + d) * DD;
            #pragma unroll 8
            for (int k = 0; k < DD; k++) {
                float hk = sh[k];
                hr = fmaf(w0[k], hk, hr);
                hz = fmaf(w1[k], hk, hz);
                hn = fmaf(w2[k], hk, hn);
            }
        }
        const float* xp = g_xproj + r * 3 * DD;
        float rg = sigmoidf_(xp[d] + hr);
        float zg = sigmoidf_(xp[DD + d] + hz);
        float ng = tanhf(xp[2 * DD + d] + rg * hn);
        float tr = (1.f - zg) * ng + zg * hd;
        float v = tr * g_cqw[(step * BB + b) * DD + d];
        #pragma unroll
        for (int off = 16; off; off >>= 1) v += __shfl_down_sync(0xFFFFFFFFu, v, off);
        if ((d & 31) == 0) red[d >> 5] = v;
        __syncthreads();
        float logit = red[0] + red[1] + b_cls[0];
        float p = sigmoidf_(logit);
        float objp = le * p;
        if (step == 0) {
            if (d == 0) atomicAdd(&g_ep0[b * EE + o], objp);
            atomicAdd(&g_hist[(size_t)(b * EE + o) * DD + d], tr * objp);
        } else {
            if (d == 0) atomicAdd(&g_ep1[b * EE + o], objp);
        }
    }
}

// ---- K6: final last_e, restore ep zeros ----------------------------------
__global__ void k_finalize(float* __restrict__ out) {
    int i = blockIdx.x * blockDim.x + threadIdx.x;
    if (i < BB * EE) {
        float x = g_ep1[i];
        out[i] = x > 1.f ? 1.f : x;
        g_ep1[i] = 0.f;
        g_ep0[i] = 0.f;
    }
}

// ---- K7: zero hist entries dirtied by step-0 scatter ---------------------
__global__ void k_cleanup(const int* __restrict__ kb) {
    int d = threadIdx.x;
    int cnt = g_cnt0;
    for (int i = blockIdx.x; i < cnt; i += gridDim.x) {
        int code = g_list0[i];
        int b = code >> 20, t = code & 0xFFFFF;
        int o = kb[3 * t + 1];
        g_hist[(size_t)(b * EE + o) * DD + d] = 0.f;
    }
}

extern "C" void kernel_launch(void* const* d_in, const int* in_sizes, int n_in,
                              void* d_out, int out_size) {
    (void)in_sizes; (void)n_in; (void)out_size;
    const float* start   = (const float*)d_in[0];
    const float* rel_emb = (const float*)d_in[1];
    const float* W_step  = (const float*)d_in[2];
    const float* b_step  = (const float*)d_in[3];
    const float* w_ih    = (const float*)d_in[4];
    const float* w_hh    = (const float*)d_in[5];
    const float* b_ih    = (const float*)d_in[6];
    const float* b_hh    = (const float*)d_in[7];
    const float* w_cls   = (const float*)d_in[8];
    const float* b_cls   = (const float*)d_in[9];
    const int*   query   = (const int*)d_in[10];
    const int*   kb      = (const int*)d_in[11];
    float* out = (float*)d_out;

    k_precompute<<<RR + 1, 192>>>(rel_emb, W_step, b_step, w_ih, b_ih, w_cls, query);
    k_scan<<<(TT + 255) / 256, 256>>>(kb, start, 0);
    k_gru<<<1024, 64>>>(kb, start, w_hh, b_hh, b_cls, 0);
    k_scan<<<(TT + 255) / 256, 256>>>(kb, start, 1);
    k_gru<<<1024, 64>>>(kb, start, w_hh, b_hh, b_cls, 1);
    k_finalize<<<(BB * EE + 255) / 256, 256>>>(out);
    k_cleanup<<<1024, 64>>>(kb);
}

// round 2
// speedup vs baseline: 1.1661x; 1.1661x over previous
#include <cuda_runtime.h>
#include <math.h>

#define BB 4
#define EE 100000
#define TT 100000
#define RR 500
#define DD 64
#define NSTEPS 2
#define EPSV 1e-6f

// Scratch (zero at module load; every executed launch restores zeros it dirtied)
__device__ __align__(16) float g_ep0[BB * EE];               // 1.6 MB
__device__ __align__(16) float g_ep1[BB * EE];               // 1.6 MB
__device__ float g_hist[(size_t)BB * EE * DD];               // 102.4 MB, sparse-touched
__device__ float g_cqw[NSTEPS * BB * DD];                    // tanh(q@W+b) * w_cls
__device__ int   g_cnt0, g_cnt1;
__device__ int   g_list0[BB * TT];                           // active (b,t) step 0
__device__ int   g_list1[BB * TT];                           // active (b,t) step 1

__device__ __forceinline__ float sigmoidf_(float x) { return 1.f / (1.f + expf(-x)); }

// ---- K1: cqw (1 block) + counter reset -----------------------------------
__global__ void k_pre(const float* __restrict__ rel_emb,
                      const float* __restrict__ W_step,
                      const float* __restrict__ b_step,
                      const float* __restrict__ w_cls,
                      const int*   __restrict__ query) {
    __shared__ float sm[BB * DD];
    int tid = threadIdx.x;  // 256
    for (int i = tid; i < BB * DD; i += blockDim.x) {
        int b = i / DD, dd = i % DD;
        sm[i] = rel_emb[query[b] * DD + dd];
    }
    __syncthreads();
    for (int idx = tid; idx < NSTEPS * BB * DD; idx += blockDim.x) {
        int s = idx / (BB * DD);
        int rem = idx % (BB * DD);
        int b = rem / DD, dd = rem % DD;
        float acc = b_step[s * DD + dd];
        const float* W = W_step + s * DD * DD + dd;
        const float* q = sm + b * DD;
        #pragma unroll 8
        for (int k = 0; k < DD; k++) acc = fmaf(q[k], W[k * DD], acc);
        g_cqw[idx] = tanhf(acc) * w_cls[dd];
    }
    if (tid == 0) { g_cnt0 = 0; g_cnt1 = 0; }
}

// ---- K2/K4: frontier scan — one thread per (edge, batch) -----------------
template <int STEP>
__global__ void k_scan(const int* __restrict__ kb, const float* __restrict__ start) {
    int idx = blockIdx.x * blockDim.x + threadIdx.x;
    if (idx >= BB * TT) return;
    int t = idx >> 2, b = idx & 3;
    int s = __ldg(&kb[3 * t]);
    float le;
    if (STEP == 0) {
        le = __ldg(&start[b * EE + s]);
    } else {
        float x = g_ep0[b * EE + s];
        le = x > 1.f ? 1.f : x;
    }
    if (le != 0.f) {
        if (STEP == 0) { int i = atomicAdd(&g_cnt0, 1); g_list0[i] = (b << 20) | t; }
        else           { int i = atomicAdd(&g_cnt1, 1); g_list1[i] = (b << 20) | t; }
    }
}

// ---- K3/K5: GRU transfer on active edges (64 threads = one edge) ---------
template <int STEP>
__global__ void k_gru(const int* __restrict__ kb, const float* __restrict__ start,
                      const float* __restrict__ rel_emb,
                      const float* __restrict__ w_ih, const float* __restrict__ b_ih,
                      const float* __restrict__ w_hh, const float* __restrict__ b_hh,
                      const float* __restrict__ b_cls) {
    __shared__ float sh[DD];    // h vector
    __shared__ float sr[DD];    // rel_emb row
    __shared__ float red[2];
    int d = threadIdx.x;  // 0..63
    const int* list = STEP ? g_list1 : g_list0;
    int cnt = STEP ? g_cnt1 : g_cnt0;
    for (int i = blockIdx.x; i < cnt; i += gridDim.x) {
        __syncthreads();  // guard smem reuse across iterations
        int code = list[i];
        int b = code >> 20, t = code & 0xFFFFF;
        int s = kb[3 * t], o = kb[3 * t + 1], r = kb[3 * t + 2];
        float le, hd;
        if (STEP == 0) {
            hd = 0.f;
            le = start[b * EE + s];
        } else {
            float ep = g_ep0[b * EE + s];
            hd = g_hist[(size_t)(b * EE + s) * DD + d] / (ep + EPSV);
            le = ep > 1.f ? 1.f : ep;
        }
        sh[d] = hd;
        sr[d] = rel_emb[r * DD + d];
        __syncthreads();
        // inline x_proj: 3 dot-64s per thread
        float xr = b_ih[d], xz = b_ih[DD + d], xn = b_ih[2 * DD + d];
        {
            const float* wi0 = w_ih + d * DD;
            const float* wi1 = w_ih + (DD + d) * DD;
            const float* wi2 = w_ih + (2 * DD + d) * DD;
            #pragma unroll 8
            for (int k = 0; k < DD; k++) {
                float rk = sr[k];
                xr = fmaf(wi0[k], rk, xr);
                xz = fmaf(wi1[k], rk, xz);
                xn = fmaf(wi2[k], rk, xn);
            }
        }
        float hr = b_hh[d], hz = b_hh[DD + d], hn = b_hh[2 * DD + d];
        if (STEP) {  // step 0: h == 0 exactly, h_proj == b_hh
            const float* w0 = w_hh + d * DD;
            const float* w1 = w_hh + (DD + d) * DD;
            const float* w2 = w_hh + (2 * DD + d) * DD;
            #pragma unroll 8
            for (int k = 0; k < DD; k++) {
                float hk = sh[k];
                hr = fmaf(w0[k], hk, hr);
                hz = fmaf(w1[k], hk, hz);
                hn = fmaf(w2[k], hk, hn);
            }
        }
        float rg = sigmoidf_(xr + hr);
        float zg = sigmoidf_(xz + hz);
        float ng = tanhf(xn + rg * hn);
        float tr = (1.f - zg) * ng + zg * hd;
        float v = tr * g_cqw[(STEP * BB + b) * DD + d];
        #pragma unroll
        for (int off = 16; off; off >>= 1) v += __shfl_down_sync(0xFFFFFFFFu, v, off);
        if ((d & 31) == 0) red[d >> 5] = v;
        __syncthreads();
        float logit = red[0] + red[1] + b_cls[0];
        float p = sigmoidf_(logit);
        float objp = le * p;
        if (STEP == 0) {
            if (d == 0) atomicAdd(&g_ep0[b * EE + o], objp);
            atomicAdd(&g_hist[(size_t)(b * EE + o) * DD + d], tr * objp);
        } else {
            if (d == 0) atomicAdd(&g_ep1[b * EE + o], objp);
        }
    }
}

// ---- K6: final last_e (float4), restore ep zeros, zero dirty hist rows ---
__global__ void k_final(float* __restrict__ out, const int* __restrict__ kb) {
    int i = blockIdx.x * blockDim.x + threadIdx.x;  // over BB*EE/4
    if (i < BB * EE / 4) {
        float4 x = ((float4*)g_ep1)[i];
        x.x = x.x > 1.f ? 1.f : x.x;
        x.y = x.y > 1.f ? 1.f : x.y;
        x.z = x.z > 1.f ? 1.f : x.z;
        x.w = x.w > 1.f ? 1.f : x.w;
        ((float4*)out)[i] = x;
        float4 z = make_float4(0.f, 0.f, 0.f, 0.f);
        ((float4*)g_ep1)[i] = z;
        ((float4*)g_ep0)[i] = z;
    }
    // cleanup of hist rows dirtied by step-0 scatter: first 64 blocks, lanes 0..63
    if (blockIdx.x < 64 && threadIdx.x < DD) {
        int d = threadIdx.x;
        int cnt = g_cnt0;
        for (int j = blockIdx.x; j < cnt; j += 64) {
            int code = g_list0[j];
            int b = code >> 20, t = code & 0xFFFFF;
            int o = kb[3 * t + 1];
            g_hist[(size_t)(b * EE + o) * DD + d] = 0.f;
        }
    }
}

extern "C" void kernel_launch(void* const* d_in, const int* in_sizes, int n_in,
                              void* d_out, int out_size) {
    (void)in_sizes; (void)n_in; (void)out_size;
    const float* start   = (const float*)d_in[0];
    const float* rel_emb = (const float*)d_in[1];
    const float* W_step  = (const float*)d_in[2];
    const float* b_step  = (const float*)d_in[3];
    const float* w_ih    = (const float*)d_in[4];
    const float* w_hh    = (const float*)d_in[5];
    const float* b_ih    = (const float*)d_in[6];
    const float* b_hh    = (const float*)d_in[7];
    const float* w_cls   = (const float*)d_in[8];
    const float* b_cls   = (const float*)d_in[9];
    const int*   query   = (const int*)d_in[10];
    const int*   kb      = (const int*)d_in[11];
    float* out = (float*)d_out;

    k_pre<<<1, 256>>>(rel_emb, W_step, b_step, w_cls, query);
    k_scan<0><<<(BB * TT + 255) / 256, 256>>>(kb, start);
    k_gru<0><<<64, 64>>>(kb, start, rel_emb, w_ih, b_ih, w_hh, b_hh, b_cls);
    k_scan<1><<<(BB * TT + 255) / 256, 256>>>(kb, start);
    k_gru<1><<<64, 64>>>(kb, start, rel_emb, w_ih, b_ih, w_hh, b_hh, b_cls);
    k_final<<<(BB * EE / 4 + 255) / 256, 256>>>(out, kb);
}